// round 16
// baseline (speedup 1.0000x reference)
#include <cuda_runtime.h>
#include <cuda_fp16.h>
#include <cstdint>
#include <math.h>

// ---------------- problem constants ----------------
#define BATCH 8192
#define IN_F  1024
#define OUT_F 1024
#define NB    8
#define KTOT  9216                       // 1024 (silu) + 8192 (basis)

// ---------------- GEMM tiling (fp16 HMMA m16n8k16) ----------------
#define BM 128
#define BN 256
#define BK 128                           // two 64-half sub-tiles per stage
#define STAGES 2
#define NITER (KTOT / BK)                // 72
#define SUB_BYTES ((BM + BN) * 128)      // 49152 per BK=64 sub-tile
#define STAGE_BYTES (2 * SUB_BYTES)      // 98304
#define BB_OFF (BM * 128)                // 16384 (within a sub-tile)
#define SMEM_DYN (STAGES * STAGE_BYTES)  // 196608 (same as R13)

// scratch (allocation-free rule: __device__ globals)
__device__ __half g_A[(size_t)BATCH * KTOT];   // 151 MB  (full fused A)
__device__ __half g_W[(size_t)OUT_F * KTOT];   //  19 MB

// ---------------- helpers ----------------
__device__ __forceinline__ uint32_t smem_u32(const void* p) {
    uint32_t a;
    asm("{ .reg .u64 t; cvta.to.shared.u64 t, %1; cvt.u32.u64 %0, t; }" : "=r"(a) : "l"(p));
    return a;
}

// bit-reinterpret __half2 -> uint32 (toolkit lacks __half2_as_uint)
__device__ __forceinline__ uint32_t h2_bits(__half2 h) {
    union { __half2 h2; uint32_t u; } cv;
    cv.h2 = h;
    return cv.u;
}

#define SWZ(o) ((o) ^ (((o) >> 3) & 0x70))

__device__ __forceinline__ void cp16(uint32_t dst, const void* src) {
    asm volatile("cp.async.cg.shared.global [%0], [%1], 16;"
                 :: "r"(dst), "l"(__cvta_generic_to_global(src)));
}
#define CP_COMMIT() asm volatile("cp.async.commit_group;" ::: "memory")
#define CP_WAIT_0() asm volatile("cp.async.wait_group 0;" ::: "memory")

#define LDSM4(r, addr) \
    asm volatile("ldmatrix.sync.aligned.m8n8.x4.shared.b16 {%0,%1,%2,%3}, [%4];" \
        : "=r"((r)[0]), "=r"((r)[1]), "=r"((r)[2]), "=r"((r)[3]) : "r"(addr))

// m16n8k16 fp16 MMA, fp32 accumulate (sm_80+ baseline — legal on plain sm_103)
__device__ __forceinline__ void mma_f16(float* c, const uint32_t* a,
                                        uint32_t b0, uint32_t b1) {
    asm volatile(
        "mma.sync.aligned.m16n8k16.row.col.f32.f16.f16.f32 "
        "{%0,%1,%2,%3}, {%4,%5,%6,%7}, {%8,%9}, {%0,%1,%2,%3};"
        : "+f"(c[0]), "+f"(c[1]), "+f"(c[2]), "+f"(c[3])
        : "r"(a[0]), "r"(a[1]), "r"(a[2]), "r"(a[3]), "r"(b0), "r"(b1));
}

// FMA-only SiLU. exp(-|v|) via range reduction + deg-4 2^u poly + exponent
// splice; 1/(1+e) via Newton, seed valid on d in [1,2]: r0 = 24/17 - 8/17*d.
__device__ __forceinline__ float silu_fma(float v) {
    float av = fminf(fabsf(v), 80.0f);
    float y = av * 1.4426950408889634f;          // av * log2(e)
    float n = floorf(y + 0.5f);
    float u = n - y;                             // [-0.5,0.5]; 2^{-y} = 2^u * 2^{-n}
    float p = fmaf(u, 0.0096181291f, 0.0555041087f);
    p = fmaf(u, p, 0.2402265069f);
    p = fmaf(u, p, 0.6931471806f);
    p = fmaf(u, p, 1.0f);                        // 2^u
    float s = __int_as_float((127 - (int)n) << 23);  // 2^{-n}
    float e = p * s;                             // exp(-av), (0,1]
    float d = 1.0f + e;                          // (1,2]
    float r = fmaf(d, -0.470588235f, 1.411764706f);  // 24/17 - 8/17*d
    r = r * (2.0f - d * r);
    r = r * (2.0f - d * r);                      // 1/(1+e)
    float sig = (v >= 0.0f) ? r : (1.0f - r);
    return v * sig;
}

// Cubic B-spline basis chunk -> 4 packed uint32 (8 halfs).
// Weights packed as a 64-bit pair and placed by a 128-bit left shift of
// 16*seg bits (funnel shifts + word selects). Bits >= 128 drop: at seg==5
// w3 lands at bit 128 and vanishes (w3==0 there anyway) — matches the
// reference's half-open-interval semantics exactly.
__device__ __forceinline__ void basis_chunk_packed(float v, uint32_t* r) {
    float xc = fminf(fmaxf(v, -1.0f), 1.0f);
    int seg = min((int)floorf((xc + 1.0f) * 2.5f), 5);
    float t = fmaf(2.5f, xc, 2.5f - (float)seg);     // in [0,1]
    float tt = t * t, ttt = tt * t;
    float omt = 1.0f - t;
    const float c6 = 1.0f / 6.0f;
    float w0 = omt * omt * omt * c6;
    float w1 = (3.0f * ttt - 6.0f * tt + 4.0f) * c6;
    float w3 = ttt * c6;
    float w2 = 1.0f - w0 - w1 - w3;                  // partition of unity

    uint32_t v0 = h2_bits(__floats2half2_rn(w0, w1));  // w0 low, w1 high
    uint32_t v1 = h2_bits(__floats2half2_rn(w2, w3));

    int b = (seg & 1) * 16;                          // sub-word shift
    int w = seg >> 1;                                // word shift 0..2
    uint32_t s0w = v0 << b;
    uint32_t s1w = __funnelshift_l(v0, v1, b);       // (v1:v0) << b, high word
    uint32_t s2w = (b == 16) ? (v1 >> 16) : 0u;      // overflow of v1

    r[0] = (w == 0) ? s0w : 0u;
    r[1] = (w == 0) ? s1w : ((w == 1) ? s0w : 0u);
    r[2] = (w == 0) ? s2w : ((w == 1) ? s1w : s0w);
    r[3] = (w == 1) ? s2w : ((w == 2) ? s1w : 0u);
}

// =====================================================================
// P0: g_A = [ h(silu(x)) | h(cubic basis(clip(x))) ], 8 x-values/thread.
// Per thread: 32B read, 16B silu store, 128B contiguous basis store.
// =====================================================================
__global__ void prep_A_kernel(const float* __restrict__ x) {
    size_t t8 = ((size_t)blockIdx.x * blockDim.x + threadIdx.x) * 8;  // linear elem idx
    int b  = (int)(t8 >> 10);        // /1024
    int i0 = (int)(t8 & 1023);       // multiple of 8
    const float* src = x + t8;
    float4 f0 = *(const float4*)(src);
    float4 f1 = *(const float4*)(src + 4);
    float xv[8] = {f0.x, f0.y, f0.z, f0.w, f1.x, f1.y, f1.z, f1.w};

    __half* row = g_A + (size_t)b * KTOT;

    // silu: 8 halfs packed into one 16B store (cvt.rn.f16x2.f32 pairs)
    uint32_t hs[4];
#pragma unroll
    for (int q = 0; q < 4; q++)
        hs[q] = h2_bits(__floats2half2_rn(silu_fma(xv[2 * q]),
                                          silu_fma(xv[2 * q + 1])));
    *(uint4*)(row + i0) = make_uint4(hs[0], hs[1], hs[2], hs[3]);

    // basis: 8 chunks x 16B = 128B contiguous, all register-resident
    uint4* dst = (uint4*)(row + IN_F + (size_t)i0 * NB);
#pragma unroll
    for (int q = 0; q < 8; q++) {
        uint32_t rc[4];
        basis_chunk_packed(xv[q], rc);
        dst[q] = make_uint4(rc[0], rc[1], rc[2], rc[3]);
    }
}

// =====================================================================
// P1: W = [ h(base_weight) | h(spline_weight) ]  (O, 9216), 8 elems/thread
// =====================================================================
__global__ void prep_W_kernel(const float* __restrict__ bw, const float* __restrict__ sw) {
    int o = blockIdx.y;
    int k8 = (blockIdx.x * blockDim.x + threadIdx.x) * 8;
    const float* src = (k8 < IN_F) ? (bw + (size_t)o * IN_F + k8)
                                   : (sw + (size_t)o * (IN_F * NB) + (k8 - IN_F));
    float4 f0 = *(const float4*)(src);
    float4 f1 = *(const float4*)(src + 4);
    uint32_t h[4];
    h[0] = h2_bits(__floats2half2_rn(f0.x, f0.y));
    h[1] = h2_bits(__floats2half2_rn(f0.z, f0.w));
    h[2] = h2_bits(__floats2half2_rn(f1.x, f1.y));
    h[3] = h2_bits(__floats2half2_rn(f1.z, f1.w));
    *(uint4*)(g_W + (size_t)o * KTOT + k8) = make_uint4(h[0], h[1], h[2], h[3]);
}

// =====================================================================
// GEMM: out[m,n] = sum_k A[m,k] * W[n,k]
// fp16 m16n8k16, BM=128 x BN=256, 8 warps (2x4), warp tile 64x64.
// BK=128 (two BK=64 sub-tiles per stage), 2-stage cp.async pipeline:
// 72 iterations -> half the barrier/wait/prime overhead of R13.
// =====================================================================
__global__ __launch_bounds__(256, 1)
void kan_gemm_kernel(float* __restrict__ out) {
    extern __shared__ char smem[];
    uint32_t sb = smem_u32(smem);
    int tid = threadIdx.x;
    int wid = tid >> 5;
    int lid = tid & 31;
    int n0 = blockIdx.x * BN;
    int m0 = blockIdx.y * BM;

    // ---- producer addressing: 24 x 16B chunks / thread / stage ----
    int rb = tid >> 3, cb = tid & 7;
    size_t aoff = (size_t)(m0 + rb) * KTOT + cb * 8;     // halfs
    size_t boff = (size_t)(n0 + rb) * KTOT + cb * 8;
    uint32_t s0 = SWZ((uint32_t)(rb * 128 + cb * 16));   // +4096 per 32 rows (swizzle-safe)

    auto load_stage = [&](int L) {
        uint32_t base = sb + (uint32_t)(L & (STAGES - 1)) * STAGE_BYTES;
#pragma unroll
        for (int h = 0; h < 2; h++) {                    // two BK=64 sub-tiles
            uint32_t bh = base + h * SUB_BYTES;
            size_t kb = (size_t)L * BK + h * 64;
#pragma unroll
            for (int u = 0; u < 4; u++)                  // A: 128 rows x 8 chunks
                cp16(bh + s0 + u * 4096, g_A + aoff + (size_t)u * 32 * KTOT + kb);
#pragma unroll
            for (int u = 0; u < 8; u++)                  // B: 256 rows x 8 chunks
                cp16(bh + BB_OFF + s0 + u * 4096, g_W + boff + (size_t)u * 32 * KTOT + kb);
        }
    };

    // ---- consumer addressing ----
    int wm = (wid >> 2) * 64;
    int wn = (wid & 3) * 64;
    int arow = ((lid & 8) ? 8 : 0) + (lid & 7);
    int akg  = (lid & 16) ? 16 : 0;
    int brow = ((lid & 16) ? 8 : 0) + (lid & 7);
    int bkg  = (lid & 8) ? 16 : 0;

    float acc[4][8][4];
#pragma unroll
    for (int mi = 0; mi < 4; mi++)
#pragma unroll
        for (int ni = 0; ni < 8; ni++)
#pragma unroll
            for (int v = 0; v < 4; v++) acc[mi][ni][v] = 0.0f;

    uint32_t af[2][4][4], bf[2][4][4];

    // ---- pipeline: 1 stage in flight, issued one iteration ahead ----
    load_stage(0); CP_COMMIT();

    for (int i = 0; i < NITER; i++) {
        CP_WAIT_0();                 // stage i resident (this thread's copies)
        __syncthreads();             // all copies visible; buf (i+1)&1 reads done (iter i-1)
        if (i + 1 < NITER) { load_stage(i + 1); CP_COMMIT(); }

        uint32_t stg = sb + (uint32_t)(i & 1) * STAGE_BYTES;

        // prime fragments for s=0 (sub-tile 0)
#pragma unroll
        for (int mi = 0; mi < 4; mi++)
            LDSM4(af[0][mi], stg + SWZ((uint32_t)((wm + mi * 16 + arow) * 128 + akg)));
#pragma unroll
        for (int p = 0; p < 4; p++)
            LDSM4(bf[0][p], stg + BB_OFF + SWZ((uint32_t)((wn + p * 16 + brow) * 128 + bkg)));

#pragma unroll
        for (int s = 0; s < 8; s++) {            // 8 x k16 steps = BK 128
            int cur = s & 1, nxt = cur ^ 1;
            if (s < 7) {                          // prefetch s+1 before s's MMAs
                uint32_t sub = stg + (uint32_t)(((s + 1) >> 2) * SUB_BYTES);
                int koff = ((s + 1) & 3) * 32;
#pragma unroll
                for (int mi = 0; mi < 4; mi++)
                    LDSM4(af[nxt][mi], sub + SWZ((uint32_t)((wm + mi * 16 + arow) * 128
                                                            + koff + akg)));
#pragma unroll
                for (int p = 0; p < 4; p++)
                    LDSM4(bf[nxt][p], sub + BB_OFF + SWZ((uint32_t)((wn + p * 16 + brow) * 128
                                                                    + koff + bkg)));
            }
#pragma unroll
            for (int mi = 0; mi < 4; mi++)
#pragma unroll
                for (int ni = 0; ni < 8; ni++)
                    mma_f16(acc[mi][ni], af[cur][mi],
                            bf[cur][ni >> 1][(ni & 1) * 2], bf[cur][ni >> 1][(ni & 1) * 2 + 1]);
        }
    }

    // ---- epilogue: c frag m16n8 f32: rows {t/4, t/4+8}, cols {2*(t%4), +1} ----
    int er = m0 + wm + (lid >> 2);
    int ec = n0 + wn + (lid & 3) * 2;
#pragma unroll
    for (int mi = 0; mi < 4; mi++) {
#pragma unroll
        for (int ni = 0; ni < 8; ni++) {
            float2 v0 = make_float2(acc[mi][ni][0], acc[mi][ni][1]);
            float2 v1 = make_float2(acc[mi][ni][2], acc[mi][ni][3]);
            *(float2*)(out + (size_t)(er + mi * 16) * OUT_F + ec + ni * 8) = v0;
            *(float2*)(out + (size_t)(er + mi * 16 + 8) * OUT_F + ec + ni * 8) = v1;
        }
    }
}

// =====================================================================
extern "C" void kernel_launch(void* const* d_in, const int* in_sizes, int n_in,
                              void* d_out, int out_size) {
    const float* x  = (const float*)d_in[0];   // (8192, 1024)
    const float* bw = (const float*)d_in[1];   // (1024, 1024)
    const float* sw = (const float*)d_in[2];   // (1024, 1024, 8)
    float* out = (float*)d_out;                // (8192, 1024)

    prep_A_kernel<<<(BATCH * IN_F / 8) / 256, 256>>>(x);
    prep_W_kernel<<<dim3(KTOT / 8 / 128, OUT_F), 128>>>(bw, sw);

    cudaFuncSetAttribute(kan_gemm_kernel, cudaFuncAttributeMaxDynamicSharedMemorySize, SMEM_DYN);
    kan_gemm_kernel<<<dim3(OUT_F / BN, BATCH / BM), 256, SMEM_DYN>>>(out);
}